// round 11
// baseline (speedup 1.0000x reference)
#include <cuda_runtime.h>
#include <math.h>
#include <stdint.h>

// B=2, DIM=32, H=W=512, FOLD=8, P=2, HDIM=96, NCLS=16, CV=96
// S=4, tile 64x64; 256 half-tile CTAs (32 rows = 2048 px each), 512 threads.
// out: center_feat [2,256,96]=49152 | labels [2,16,256]=8192 | spix_map [2,512,512]=524288

__device__ float  d_cen[128][159][4];    // pooled quadrant means
__device__ float4 d_scst[256 * 2048];    // per-pixel static scores, per half-CTA
__device__ float  d_num2[256][388];      // iter-0 partials per half-CTA (den at 384+s)
__device__ float  d_onum2[256][388];     // iter-1 partials per half-CTA (wden at 384+s)
__device__ int    d_cnt2[256][64];       // label hist partials per half-CTA

__device__ __forceinline__ float wredsum(float v) {
#pragma unroll
    for (int o = 16; o; o >>= 1) v += __shfl_xor_sync(0xffffffffu, v, o);
    return v;
}
__device__ __forceinline__ float red8(float v) {
#pragma unroll
    for (int o = 4; o; o >>= 1) v += __shfl_xor_sync(0xffffffffu, v, o);
    return v;
}

// ================= Kernel 1: pooling (proven, ~74% DRAM) =================
__global__ void __launch_bounds__(256)
pool_kernel(const float* __restrict__ x, const float* __restrict__ feat,
            const float* __restrict__ sdf)
{
    __shared__ float part[8][16];
    const int id = blockIdx.x;
    const int b = id / 636, rem = id % 636;
    const int ch = rem >> 2, qtr = rem & 3;
    const float* src;
    if (ch < 32)      src = x    + (((size_t)(b * 32 + ch)) << 18);
    else if (ch < 63) src = sdf  + (((size_t)(b * 31 + (ch - 32))) << 18);
    else              src = feat + (((size_t)(b * 96 + (ch - 63))) << 18);
    src += qtr * 128 * 512;

    const int w = threadIdx.x >> 5, lane = threadIdx.x & 31;
    const int row0 = (w >> 1) * 32 + (w & 1) * 16;

    float accj[4] = {0.f, 0.f, 0.f, 0.f};
    const float* rbase = src + row0 * 512 + lane * 4;
#pragma unroll 4
    for (int r = 0; r < 16; r++) {
        const float* rp = rbase + r * 512;
#pragma unroll
        for (int j = 0; j < 4; j++) {
            float4 v = *(const float4*)(rp + j * 128);
            accj[j] += (v.x + v.y) + (v.z + v.w);
        }
    }
#pragma unroll
    for (int j = 0; j < 4; j++) {
        float s = red8(accj[j]);
        if ((lane & 7) == 0) part[w][j * 4 + (lane >> 3)] = s;
    }
    __syncthreads();
    if (threadIdx.x < 64) {
        int qr = threadIdx.x >> 4, cb = threadIdx.x & 15;
        float val = (part[2 * qr][cb] + part[2 * qr + 1][cb]) * (1.f / 1024.f);
        int gqr = qtr * 4 + qr;
        int f1 = gqr >> 1, qy = gqr & 1;
        int tile = b * 64 + f1 * 8 + (cb >> 1);
        d_cen[tile][ch][qy * 2 + (cb & 1)] = val;
    }
}

// ================= Kernel 2: iter-0 (half-tile, 2 CTAs/SM) =================
__global__ void __launch_bounds__(512, 2)
iter0_kernel(const float* __restrict__ x, const float* __restrict__ feat,
             const float* __restrict__ sdf, const float* __restrict__ Wf,
             const float* __restrict__ bf, const float* __restrict__ Wsdf,
             const float* __restrict__ bsdf)
{
    __shared__ __align__(16) float4 a4[2][512];
    __shared__ __align__(16) float4 cen4[160];
    __shared__ __align__(16) float4 cdf4[96], csf4[96], g4[32], q4[32];
    __shared__ float num[97][4];
    __shared__ float Cs[4], n0[4];

    const int gcta = blockIdx.x;
    const int tile = gcta >> 1;
    const int half = gcta & 1;
    const int b    = tile >> 6;
    const int f1   = (tile >> 3) & 7;
    const int f2   = tile & 7;
    const int tid  = threadIdx.x;
    const int wid  = tid >> 5;
    const int lane = tid & 31;
    const int hbase = f1 * 64 * 512 + f2 * 64 + half * 32 * 512;

    const float* xb = x    + (((size_t)(b * 32)) << 18) + hbase;
    const float* sb = sdf  + (((size_t)(b * 31)) << 18) + hbase;
    const float* fb = feat + (((size_t)(b * 96)) << 18) + hbase;

    if (tid < 388) ((float*)num)[tid] = 0.f;
    if (tid >= 388 && tid < 388 + 248) { /* idle */ }
    for (int i = tid; i < 636; i += 512) ((float*)cen4)[i] = ((const float*)d_cen[tile])[i];
    __syncthreads();

    // per-tile derived quantities (proven R3 code; redundant per half-CTA)
    if (tid < 384) {
        int j = tid >> 2, s = tid & 3;
        const float* wr = Wf + j * 32;
        float a = bf[j];
#pragma unroll 8
        for (int c = 0; c < 32; c++) a = fmaf(wr[c], ((const float*)&cen4[c])[s], a);
        ((float*)&cdf4[j])[s] = a;
        const float* wr2 = Wsdf + j * 31;
        float a2 = bsdf[j];
#pragma unroll 8
        for (int c = 0; c < 31; c++) a2 = fmaf(wr2[c], ((const float*)&cen4[32 + c])[s], a2);
        ((float*)&csf4[j])[s] = a2;
    }
    __syncthreads();
    if (tid < 128) {
        int c = tid >> 2, s = tid & 3;
        float a = 0.f;
        for (int j = 0; j < 96; j++) a = fmaf(Wf[j * 32 + c], ((const float*)&cdf4[j])[s], a);
        ((float*)&g4[c])[s] = a;
    } else if (tid < 252) {
        int t2 = tid - 128; int c = t2 >> 2, s = t2 & 3;
        float a = 0.f;
        for (int j = 0; j < 96; j++) a = fmaf(Wsdf[j * 31 + c], ((const float*)&csf4[j])[s], a);
        ((float*)&q4[c])[s] = a;
    } else if (tid >= 256 && tid < 260) {
        int s = tid - 256;
        float kf = 0.f, ks = 0.f, nd = 0.f, ns = 0.f;
        for (int j = 0; j < 96; j++) {
            float d = ((const float*)&cdf4[j])[s];
            float e = ((const float*)&csf4[j])[s];
            kf = fmaf(bf[j], d, kf); ks = fmaf(bsdf[j], e, ks);
            nd = fmaf(d, d, nd);     ns = fmaf(e, e, ns);
        }
        Cs[s] = 2.f * kf + 2.f * ks - nd - ns;
    } else if (tid >= 260 && tid < 264) {
        int s = tid - 260;
        float a = 0.f;
        for (int c = 0; c < 96; c++) { float v = ((const float*)&cen4[63 + c])[s]; a = fmaf(v, v, a); }
        n0[s] = a;
    }
    __syncthreads();

    const float C0 = Cs[0], C1 = Cs[1], C2 = Cs[2], C3 = Cs[3];
    const float m0 = n0[0], m1 = n0[1], m2 = n0[2], m3 = n0[3];

    float pd0 = 0.f, pd1 = 0.f, pd2 = 0.f, pd3 = 0.f;

    for (int ck = 0; ck < 4; ck++) {
        const int bb  = ck & 1;
        const int p   = ck * 512 + tid;
        const int pix = (p >> 6) * 512 + (p & 63);
        float r0 = 0.f, r1 = 0.f, r2 = 0.f, r3 = 0.f;
        {
            const float* xp = xb + pix;
#pragma unroll 16
            for (int c = 0; c < 32; c++) {
                float v = xp[((size_t)c) << 18];
                float4 g = g4[c];
                r0 = fmaf(v, g.x, r0); r1 = fmaf(v, g.y, r1);
                r2 = fmaf(v, g.z, r2); r3 = fmaf(v, g.w, r3);
            }
            const float* sp = sb + pix;
#pragma unroll 16
            for (int c = 0; c < 31; c++) {
                float v = sp[((size_t)c) << 18];
                float4 g = q4[c];
                r0 = fmaf(v, g.x, r0); r1 = fmaf(v, g.y, r1);
                r2 = fmaf(v, g.z, r2); r3 = fmaf(v, g.w, r3);
            }
        }
        float st0 = 2.f * r0 + C0, st1 = 2.f * r1 + C1;
        float st2 = 2.f * r2 + C2, st3 = 2.f * r3 + C3;
        d_scst[gcta * 2048 + p] = make_float4(st0, st1, st2, st3);

        float f0 = 0.f, f1_ = 0.f, f2_ = 0.f, f3 = 0.f;
        {
            const float* fp = fb + pix;
#pragma unroll 16
            for (int c = 0; c < 96; c++) {
                float v = fp[((size_t)c) << 18];
                float4 g = cen4[63 + c];
                f0 = fmaf(v, g.x, f0); f1_ = fmaf(v, g.y, f1_);
                f2_ = fmaf(v, g.z, f2_); f3 = fmaf(v, g.w, f3);
            }
        }
        float q0 = st0 + 2.f * f0 - m0;
        float q1 = st1 + 2.f * f1_ - m1;
        float q2 = st2 + 2.f * f2_ - m2;
        float q3 = st3 + 2.f * f3 - m3;
        float mx = fmaxf(fmaxf(q0, q1), fmaxf(q2, q3));
        float e0 = __expf(q0 - mx), e1 = __expf(q1 - mx);
        float e2 = __expf(q2 - mx), e3 = __expf(q3 - mx);
        float inv = 1.f / (e0 + e1 + e2 + e3);
        float a0 = e0 * inv, a1 = e1 * inv, a2 = e2 * inv, a3 = e3 * inv;
        a4[bb][tid] = make_float4(a0, a1, a2, a3);
        pd0 += a0; pd1 += a1; pd2 += a2; pd3 += a3;
        __syncthreads();

        // accumulation: warp wid owns channels 6*wid..6*wid+5 (audited R9 code)
        float ac[24];
#pragma unroll
        for (int k = 0; k < 24; k++) ac[k] = 0.f;
#pragma unroll
        for (int cl = 0; cl < 6; cl++) {
            const float* cp = fb + (((size_t)(wid * 6 + cl)) << 18) + ck * 8 * 512 + lane;
#pragma unroll
            for (int seg = 0; seg < 16; seg++) {
                float v = cp[(seg >> 1) * 512 + (seg & 1) * 32];
                float4 a = a4[bb][seg * 32 + lane];
                ac[cl * 4 + 0] = fmaf(v, a.x, ac[cl * 4 + 0]);
                ac[cl * 4 + 1] = fmaf(v, a.y, ac[cl * 4 + 1]);
                ac[cl * 4 + 2] = fmaf(v, a.z, ac[cl * 4 + 2]);
                ac[cl * 4 + 3] = fmaf(v, a.w, ac[cl * 4 + 3]);
            }
        }
#pragma unroll
        for (int k = 0; k < 24; k++) {
            float r = wredsum(ac[k]);
            if (lane == 0) num[wid * 6 + (k >> 2)][k & 3] += r;
        }
        // no trailing barrier: next chunk uses the other a4 buffer
    }
    pd0 = wredsum(pd0); pd1 = wredsum(pd1); pd2 = wredsum(pd2); pd3 = wredsum(pd3);
    if (lane == 0) {
        atomicAdd(&num[96][0], pd0); atomicAdd(&num[96][1], pd1);
        atomicAdd(&num[96][2], pd2); atomicAdd(&num[96][3], pd3);
    }
    __syncthreads();
    if (tid < 388) d_num2[gcta][tid] = ((const float*)num)[tid];
}

// ================= Kernel 3: iter-1 (half-tile, 2 CTAs/SM) =================
__global__ void __launch_bounds__(512, 2)
iter1_kernel(const float* __restrict__ feat, const int* __restrict__ gt,
             float* __restrict__ out)
{
    __shared__ __align__(16) float4 a4[2][512];
    __shared__ __align__(16) float4 cpf1[96];
    __shared__ float onum[97][4];
    __shared__ float den[4], n1[4];
    __shared__ int   cnt[64];

    const int gcta = blockIdx.x;
    const int tile = gcta >> 1;
    const int half = gcta & 1;
    const int t2   = tile * 2;
    const int b    = tile >> 6;
    const int f1   = (tile >> 3) & 7;
    const int f2   = tile & 7;
    const int tid  = threadIdx.x;
    const int wid  = tid >> 5;
    const int lane = tid & 31;
    const int hbase = f1 * 64 * 512 + f2 * 64 + half * 32 * 512;

    const float* fb = feat + (((size_t)(b * 96)) << 18) + hbase;

    if (tid < 388) ((float*)onum)[tid] = 0.f;
    if (tid < 64)  cnt[tid] = 0;
    if (tid >= 448 && tid < 452) {
        int s = tid - 448;
        den[s] = d_num2[t2][384 + s] + d_num2[t2 + 1][384 + s] + 1e-16f;
    }
    __syncthreads();
    if (tid < 384)
        ((float*)cpf1)[tid] = (d_num2[t2][tid] + d_num2[t2 + 1][tid]) / den[tid & 3];
    __syncthreads();
    if (tid < 4) {
        float a = 0.f;
        for (int c = 0; c < 96; c++) { float v = ((const float*)&cpf1[c])[tid]; a = fmaf(v, v, a); }
        n1[tid] = a;
    }
    __syncthreads();

    const float u0 = n1[0], u1 = n1[1], u2 = n1[2], u3 = n1[3];
    const int tloc4 = (f1 * 8 + f2) * 4;
    const int* gtb = gt + (size_t)b * 262144 + hbase;
    float* spix = out + 57344 + (size_t)b * 262144 + hbase;

    float pw0 = 0.f, pw1 = 0.f, pw2 = 0.f, pw3 = 0.f;

    for (int ck = 0; ck < 4; ck++) {
        const int bb  = ck & 1;
        const int p   = ck * 512 + tid;
        const int pix = (p >> 6) * 512 + (p & 63);
        float4 st = d_scst[gcta * 2048 + p];
        float f0 = 0.f, f1_ = 0.f, f2_ = 0.f, f3 = 0.f;
        const float* fp = fb + pix;
#pragma unroll 16
        for (int c = 0; c < 96; c++) {
            float v = fp[((size_t)c) << 18];
            float4 g = cpf1[c];
            f0 = fmaf(v, g.x, f0); f1_ = fmaf(v, g.y, f1_);
            f2_ = fmaf(v, g.z, f2_); f3 = fmaf(v, g.w, f3);
        }
        float q0 = st.x + 2.f * f0 - u0;
        float q1 = st.y + 2.f * f1_ - u1;
        float q2 = st.z + 2.f * f2_ - u2;
        float q3 = st.w + 2.f * f3 - u3;
        int ss = 0; float best = q0;                 // first-max tie rule (matches jnp.argmax)
        if (q1 > best) { best = q1; ss = 1; }
        if (q2 > best) { best = q2; ss = 2; }
        if (q3 > best) { best = q3; ss = 3; }
        float w = 1.f / (__expf(q0 - best) + __expf(q1 - best)
                       + __expf(q2 - best) + __expf(q3 - best));
        float4 mm;
        mm.x = (ss == 0) ? w : 0.f; mm.y = (ss == 1) ? w : 0.f;
        mm.z = (ss == 2) ? w : 0.f; mm.w = (ss == 3) ? w : 0.f;
        a4[bb][tid] = mm;
        pw0 += mm.x; pw1 += mm.y; pw2 += mm.z; pw3 += mm.w;
        int gv = gtb[pix];
        atomicAdd(&cnt[ss * 16 + gv], 1);
        spix[pix] = (float)(tloc4 + ss);
        __syncthreads();

        float ac[24];
#pragma unroll
        for (int k = 0; k < 24; k++) ac[k] = 0.f;
#pragma unroll
        for (int cl = 0; cl < 6; cl++) {
            const float* cp = fb + (((size_t)(wid * 6 + cl)) << 18) + ck * 8 * 512 + lane;
#pragma unroll
            for (int seg = 0; seg < 16; seg++) {
                float v = cp[(seg >> 1) * 512 + (seg & 1) * 32];
                float4 a = a4[bb][seg * 32 + lane];
                ac[cl * 4 + 0] = fmaf(v, a.x, ac[cl * 4 + 0]);
                ac[cl * 4 + 1] = fmaf(v, a.y, ac[cl * 4 + 1]);
                ac[cl * 4 + 2] = fmaf(v, a.z, ac[cl * 4 + 2]);
                ac[cl * 4 + 3] = fmaf(v, a.w, ac[cl * 4 + 3]);
            }
        }
#pragma unroll
        for (int k = 0; k < 24; k++) {
            float r = wredsum(ac[k]);
            if (lane == 0) onum[wid * 6 + (k >> 2)][k & 3] += r;
        }
    }
    pw0 = wredsum(pw0); pw1 = wredsum(pw1); pw2 = wredsum(pw2); pw3 = wredsum(pw3);
    if (lane == 0) {
        atomicAdd(&onum[96][0], pw0); atomicAdd(&onum[96][1], pw1);
        atomicAdd(&onum[96][2], pw2); atomicAdd(&onum[96][3], pw3);
    }
    __syncthreads();
    if (tid < 388) d_onum2[gcta][tid] = ((const float*)onum)[tid];
    if (tid < 64)  d_cnt2[gcta][tid]  = cnt[tid];
}

// ================= Kernel 4: final outputs (proven R6 code) =================
__global__ void __launch_bounds__(384)
final_kernel(float* __restrict__ out)
{
    const int tile = blockIdx.x, tid = threadIdx.x;
    const int t2 = tile * 2;
    const int b = tile >> 6;
    const int tloc4 = (tile & 63) * 4;
    __shared__ float wden[4];
    if (tid < 4)
        wden[tid] = d_onum2[t2][384 + tid] + d_onum2[t2 + 1][384 + tid] + 1.f;
    __syncthreads();
    {
        int c = tid >> 2, s = tid & 3;
        float tot = d_onum2[t2][tid] + d_onum2[t2 + 1][tid];
        float vc  = d_cen[tile][63 + c][s];
        out[(size_t)b * 24576 + (size_t)(tloc4 + s) * 96 + c] = (tot + vc) / wden[s];
    }
    if (tid < 64) {
        int s = tid >> 4, cls = tid & 15;
        int cnt = d_cnt2[t2][tid] + d_cnt2[t2 + 1][tid];
        out[49152 + (size_t)b * 4096 + (size_t)cls * 256 + tloc4 + s] = (float)cnt;
    }
}

extern "C" void kernel_launch(void* const* d_in, const int* in_sizes, int n_in,
                              void* d_out, int out_size) {
    const float* x    = (const float*)d_in[0];
    const float* feat = (const float*)d_in[1];
    const float* sdf  = (const float*)d_in[2];
    const float* Wf   = (const float*)d_in[3];
    const float* bf   = (const float*)d_in[4];
    const float* Wsdf = (const float*)d_in[5];
    const float* bsdf = (const float*)d_in[6];
    const int*   gt   = (const int*)d_in[7];
    float* out = (float*)d_out;

    pool_kernel<<<1272, 256>>>(x, feat, sdf);
    iter0_kernel<<<256, 512>>>(x, feat, sdf, Wf, bf, Wsdf, bsdf);
    iter1_kernel<<<256, 512>>>(feat, gt, out);
    final_kernel<<<128, 384>>>(out);
}

// round 12
// speedup vs baseline: 1.3440x; 1.3440x over previous
#include <cuda_runtime.h>
#include <math.h>

// B=2, DIM=32, H=W=512, FOLD=8, P=2, HDIM=96, NCLS=16, CV=96
// S=4, tile 64x64, N=4096 px/tile, 128 tiles. One CTA per tile, 1024 threads,
// split into two independent 512-thread groups (rows 0-31 / 32-63) with
// group-local named barriers so scoring (DRAM) and accumulation (L2) overlap.
// out: center_feat [2,256,96]=49152 | labels [2,16,256]=8192 | spix_map [2,512,512]=524288

struct SmemLayout {
    float4 scst[4096];      // per-pixel static (x+sdf) scores
    float4 a4[2][2][512];   // [group][buf][gtid] softmax/masked weights
    float4 cen4[160];       // pooled quadrant means: x[0..31], sdf[32..62], feat[63..158]
    float4 cdf4[96];
    float4 csf4[96];
    float4 g4[32];
    float4 q4[32];
    float4 cpf1[96];
    float  num[2][97][4];   // iter-0 partials per group (unused [96] row spare)
    float  onum[2][97][4];  // iter-1 partials per group
    float  Cs[4], n0[4], n1[4], den[4], wden[4];
    int    cnt[64];
};

__device__ __forceinline__ float wredsum(float v) {
#pragma unroll
    for (int o = 16; o; o >>= 1) v += __shfl_xor_sync(0xffffffffu, v, o);
    return v;
}
__device__ __forceinline__ void gbar(int g) {       // group-local named barrier
    asm volatile("bar.sync %0, %1;" :: "r"(g + 1), "r"(512) : "memory");
}

__global__ void __launch_bounds__(1024, 1)
cluster_kernel(const float* __restrict__ x, const float* __restrict__ feat,
               const float* __restrict__ sdf, const float* __restrict__ Wf,
               const float* __restrict__ bf, const float* __restrict__ Wsdf,
               const float* __restrict__ bsdf, const int* __restrict__ gt,
               float* __restrict__ out)
{
    extern __shared__ char smem_raw[];
    SmemLayout* sh = reinterpret_cast<SmemLayout*>(smem_raw);

    const int tile = blockIdx.x;
    const int b    = tile >> 6;
    const int f1   = (tile >> 3) & 7;
    const int f2   = tile & 7;
    const int tid  = threadIdx.x;
    const int wid  = tid >> 5;
    const int lane = tid & 31;
    const int g    = tid >> 9;          // warp-group 0/1
    const int gtid = tid & 511;
    const int gwid = gtid >> 5;         // 0..15 within group
    const int base = f1 * 64 * 512 + f2 * 64;

    // zero reduction scratch
    for (int i = tid; i < 1552; i += 1024) ((float*)sh->num)[i] = 0.f;
    if (tid < 4) { sh->den[tid] = 0.f; sh->wden[tid] = 0.f; }
    if (tid < 64) sh->cnt[tid] = 0;

    // ---------------- Phase 1: quadrant pooling (float4) ----------------
    for (int ch = wid; ch < 159; ch += 32) {
        const float* src;
        if (ch < 32)      src = x    + (((size_t)(b * 32 + ch)) << 18);
        else if (ch < 63) src = sdf  + (((size_t)(b * 31 + (ch - 32))) << 18);
        else              src = feat + (((size_t)(b * 96 + (ch - 63))) << 18);
        src += base;
        float acc[4];
#pragma unroll
        for (int q = 0; q < 4; q++) {
            const float* p2 = src + (q >> 1) * 32 * 512 + (q & 1) * 32
                                  + (lane >> 3) * 512 + (lane & 7) * 4;
            float a = 0.f;
#pragma unroll
            for (int i = 0; i < 8; i++) {
                float4 v = *(const float4*)(p2 + i * 4 * 512);
                a += (v.x + v.y) + (v.z + v.w);
            }
            acc[q] = a;
        }
#pragma unroll
        for (int q = 0; q < 4; q++) acc[q] = wredsum(acc[q]);
        if (lane == 0)
            sh->cen4[ch] = make_float4(acc[0] * (1.f / 1024.f), acc[1] * (1.f / 1024.f),
                                       acc[2] * (1.f / 1024.f), acc[3] * (1.f / 1024.f));
    }
    __syncthreads();

    // ---------------- Phase 2: per-tile derived quantities ----------------
    if (tid < 384) {
        int j = tid >> 2, s = tid & 3;
        const float* wr = Wf + j * 32;
        float a = bf[j];
#pragma unroll 8
        for (int c = 0; c < 32; c++) a = fmaf(wr[c], ((const float*)&sh->cen4[c])[s], a);
        ((float*)&sh->cdf4[j])[s] = a;
        const float* wr2 = Wsdf + j * 31;
        float a2 = bsdf[j];
#pragma unroll 8
        for (int c = 0; c < 31; c++) a2 = fmaf(wr2[c], ((const float*)&sh->cen4[32 + c])[s], a2);
        ((float*)&sh->csf4[j])[s] = a2;
    }
    __syncthreads();
    if (tid < 128) {
        int c = tid >> 2, s = tid & 3;
        float a = 0.f;
        for (int j = 0; j < 96; j++) a = fmaf(Wf[j * 32 + c], ((const float*)&sh->cdf4[j])[s], a);
        ((float*)&sh->g4[c])[s] = a;
    } else if (tid < 252) {
        int t2 = tid - 128; int c = t2 >> 2, s = t2 & 3;
        float a = 0.f;
        for (int j = 0; j < 96; j++) a = fmaf(Wsdf[j * 31 + c], ((const float*)&sh->csf4[j])[s], a);
        ((float*)&sh->q4[c])[s] = a;
    } else if (tid >= 256 && tid < 260) {
        int s = tid - 256;
        float kf = 0.f, ks = 0.f, nd = 0.f, ns = 0.f;
        for (int j = 0; j < 96; j++) {
            float d = ((const float*)&sh->cdf4[j])[s];
            float e = ((const float*)&sh->csf4[j])[s];
            kf = fmaf(bf[j], d, kf); ks = fmaf(bsdf[j], e, ks);
            nd = fmaf(d, d, nd);     ns = fmaf(e, e, ns);
        }
        sh->Cs[s] = 2.f * kf + 2.f * ks - nd - ns;
    } else if (tid >= 260 && tid < 264) {
        int s = tid - 260;
        float a = 0.f;
        for (int c = 0; c < 96; c++) { float v = ((const float*)&sh->cen4[63 + c])[s]; a = fmaf(v, v, a); }
        sh->n0[s] = a;
    }
    __syncthreads();

    const float C0 = sh->Cs[0], C1 = sh->Cs[1], C2 = sh->Cs[2], C3 = sh->Cs[3];
    const float m0 = sh->n0[0], m1 = sh->n0[1], m2 = sh->n0[2], m3 = sh->n0[3];

    const float* xb = x    + (((size_t)(b * 32)) << 18) + base;
    const float* sb = sdf  + (((size_t)(b * 31)) << 18) + base;
    const float* fb = feat + (((size_t)(b * 96)) << 18) + base;

    // 6 accumulation channel pointers for this warp (channels gwid*6 .. +5)
    const float* fcl[6];
#pragma unroll
    for (int cl = 0; cl < 6; cl++)
        fcl[cl] = fb + (((size_t)(gwid * 6 + cl)) << 18);

    // ---------------- Phase 3: iter-0 (group-local pipeline) ----------------
    float pd0 = 0.f, pd1 = 0.f, pd2 = 0.f, pd3 = 0.f;

    for (int ck = 0; ck < 4; ck++) {
        const int bb  = ck & 1;
        const int p   = (g << 11) + (ck << 9) + gtid;    // group rows: g*32 + ck*8 ..
        const int pix = (p >> 6) * 512 + (p & 63);
        float r0 = 0.f, r1 = 0.f, r2 = 0.f, r3 = 0.f;
        {
            const float* xp = xb + pix;
#pragma unroll 16
            for (int c = 0; c < 32; c++) {
                float v = xp[((size_t)c) << 18];
                float4 gg = sh->g4[c];
                r0 = fmaf(v, gg.x, r0); r1 = fmaf(v, gg.y, r1);
                r2 = fmaf(v, gg.z, r2); r3 = fmaf(v, gg.w, r3);
            }
            const float* sp = sb + pix;
#pragma unroll 16
            for (int c = 0; c < 31; c++) {
                float v = sp[((size_t)c) << 18];
                float4 gg = sh->q4[c];
                r0 = fmaf(v, gg.x, r0); r1 = fmaf(v, gg.y, r1);
                r2 = fmaf(v, gg.z, r2); r3 = fmaf(v, gg.w, r3);
            }
        }
        float st0 = 2.f * r0 + C0, st1 = 2.f * r1 + C1;
        float st2 = 2.f * r2 + C2, st3 = 2.f * r3 + C3;
        sh->scst[p] = make_float4(st0, st1, st2, st3);

        float f0 = 0.f, f1_ = 0.f, f2_ = 0.f, f3 = 0.f;
        {
            const float* fp = fb + pix;
#pragma unroll 16
            for (int c = 0; c < 96; c++) {
                float v = fp[((size_t)c) << 18];
                float4 gg = sh->cen4[63 + c];
                f0 = fmaf(v, gg.x, f0); f1_ = fmaf(v, gg.y, f1_);
                f2_ = fmaf(v, gg.z, f2_); f3 = fmaf(v, gg.w, f3);
            }
        }
        float q0 = st0 + 2.f * f0 - m0;
        float q1 = st1 + 2.f * f1_ - m1;
        float q2 = st2 + 2.f * f2_ - m2;
        float q3 = st3 + 2.f * f3 - m3;
        float mx = fmaxf(fmaxf(q0, q1), fmaxf(q2, q3));
        float e0 = __expf(q0 - mx), e1 = __expf(q1 - mx);
        float e2 = __expf(q2 - mx), e3 = __expf(q3 - mx);
        float inv = 1.f / (e0 + e1 + e2 + e3);
        float a0 = e0 * inv, a1 = e1 * inv, a2 = e2 * inv, a3 = e3 * inv;
        sh->a4[g][bb][gtid] = make_float4(a0, a1, a2, a3);
        pd0 += a0; pd1 += a1; pd2 += a2; pd3 += a3;
        gbar(g);                       // group-local: a4[g][bb] ready

        // accumulation over this group's 8-row chunk: 1 LDS.128 + 6 LDG + 24 FMA / seg
        float ac[24];
#pragma unroll
        for (int k = 0; k < 24; k++) ac[k] = 0.f;
        const int rbase = (g * 32 + ck * 8) * 512 + lane;
#pragma unroll 4
        for (int seg = 0; seg < 16; seg++) {
            const int off = rbase + (seg >> 1) * 512 + (seg & 1) * 32;
            float4 a = sh->a4[g][bb][seg * 32 + lane];
#pragma unroll
            for (int cl = 0; cl < 6; cl++) {
                float v = fcl[cl][off];
                ac[cl * 4 + 0] = fmaf(v, a.x, ac[cl * 4 + 0]);
                ac[cl * 4 + 1] = fmaf(v, a.y, ac[cl * 4 + 1]);
                ac[cl * 4 + 2] = fmaf(v, a.z, ac[cl * 4 + 2]);
                ac[cl * 4 + 3] = fmaf(v, a.w, ac[cl * 4 + 3]);
            }
        }
#pragma unroll
        for (int k = 0; k < 24; k++) {
            float r = wredsum(ac[k]);
            if (lane == 0) sh->num[g][gwid * 6 + (k >> 2)][k & 3] += r;
        }
        // no trailing barrier: next chunk writes the other buffer
    }
    pd0 = wredsum(pd0); pd1 = wredsum(pd1); pd2 = wredsum(pd2); pd3 = wredsum(pd3);
    if (lane == 0) {
        atomicAdd(&sh->den[0], pd0); atomicAdd(&sh->den[1], pd1);
        atomicAdd(&sh->den[2], pd2); atomicAdd(&sh->den[3], pd3);
    }
    __syncthreads();

    // centroid update (fixed-order group sum -> deterministic)
    if (tid < 384) {
        int c = tid >> 2, s = tid & 3;
        float tot = sh->num[0][c][s] + sh->num[1][c][s];
        ((float*)sh->cpf1)[tid] = tot / (sh->den[s] + 1e-16f);
    }
    __syncthreads();
    if (tid < 4) {
        float a = 0.f;
        for (int c = 0; c < 96; c++) { float v = ((const float*)&sh->cpf1[c])[tid]; a = fmaf(v, v, a); }
        sh->n1[tid] = a;
    }
    __syncthreads();

    const float u0 = sh->n1[0], u1 = sh->n1[1], u2 = sh->n1[2], u3 = sh->n1[3];
    const int tloc4 = (f1 * 8 + f2) * 4;
    const int* gtb = gt + (size_t)b * 262144 + base;
    float* spix = out + 57344 + (size_t)b * 262144 + base;

    // ---------------- Phase 4: iter-1 (group-local pipeline) ----------------
    float pw0 = 0.f, pw1 = 0.f, pw2 = 0.f, pw3 = 0.f;

    for (int ck = 0; ck < 4; ck++) {
        const int bb  = ck & 1;
        const int p   = (g << 11) + (ck << 9) + gtid;
        const int pix = (p >> 6) * 512 + (p & 63);
        float4 st = sh->scst[p];
        float f0 = 0.f, f1_ = 0.f, f2_ = 0.f, f3 = 0.f;
        const float* fp = fb + pix;
#pragma unroll 16
        for (int c = 0; c < 96; c++) {
            float v = fp[((size_t)c) << 18];
            float4 gg = sh->cpf1[c];
            f0 = fmaf(v, gg.x, f0); f1_ = fmaf(v, gg.y, f1_);
            f2_ = fmaf(v, gg.z, f2_); f3 = fmaf(v, gg.w, f3);
        }
        float q0 = st.x + 2.f * f0 - u0;
        float q1 = st.y + 2.f * f1_ - u1;
        float q2 = st.z + 2.f * f2_ - u2;
        float q3 = st.w + 2.f * f3 - u3;
        int ss = 0; float best = q0;                 // first-max tie rule (matches jnp.argmax)
        if (q1 > best) { best = q1; ss = 1; }
        if (q2 > best) { best = q2; ss = 2; }
        if (q3 > best) { best = q3; ss = 3; }
        float w = 1.f / (__expf(q0 - best) + __expf(q1 - best)
                       + __expf(q2 - best) + __expf(q3 - best));
        float4 mm;
        mm.x = (ss == 0) ? w : 0.f; mm.y = (ss == 1) ? w : 0.f;
        mm.z = (ss == 2) ? w : 0.f; mm.w = (ss == 3) ? w : 0.f;
        sh->a4[g][bb][gtid] = mm;
        pw0 += mm.x; pw1 += mm.y; pw2 += mm.z; pw3 += mm.w;
        int gv = gtb[pix];
        atomicAdd(&sh->cnt[ss * 16 + gv], 1);
        spix[pix] = (float)(tloc4 + ss);
        gbar(g);

        float ac[24];
#pragma unroll
        for (int k = 0; k < 24; k++) ac[k] = 0.f;
        const int rbase = (g * 32 + ck * 8) * 512 + lane;
#pragma unroll 4
        for (int seg = 0; seg < 16; seg++) {
            const int off = rbase + (seg >> 1) * 512 + (seg & 1) * 32;
            float4 a = sh->a4[g][bb][seg * 32 + lane];
#pragma unroll
            for (int cl = 0; cl < 6; cl++) {
                float v = fcl[cl][off];
                ac[cl * 4 + 0] = fmaf(v, a.x, ac[cl * 4 + 0]);
                ac[cl * 4 + 1] = fmaf(v, a.y, ac[cl * 4 + 1]);
                ac[cl * 4 + 2] = fmaf(v, a.z, ac[cl * 4 + 2]);
                ac[cl * 4 + 3] = fmaf(v, a.w, ac[cl * 4 + 3]);
            }
        }
#pragma unroll
        for (int k = 0; k < 24; k++) {
            float r = wredsum(ac[k]);
            if (lane == 0) sh->onum[g][gwid * 6 + (k >> 2)][k & 3] += r;
        }
    }
    pw0 = wredsum(pw0); pw1 = wredsum(pw1); pw2 = wredsum(pw2); pw3 = wredsum(pw3);
    if (lane == 0) {
        atomicAdd(&sh->wden[0], pw0); atomicAdd(&sh->wden[1], pw1);
        atomicAdd(&sh->wden[2], pw2); atomicAdd(&sh->wden[3], pw3);
    }
    __syncthreads();

    // ---------------- Phase 5: final writes ----------------
    if (tid < 384) {
        int c = tid >> 2, s = tid & 3;
        float ov = sh->onum[0][c][s] + sh->onum[1][c][s];
        float vc = ((const float*)&sh->cen4[63 + c])[s];
        float res = (ov + vc) / (sh->wden[s] + 1.f);
        out[(size_t)b * 24576 + (size_t)(tloc4 + s) * 96 + c] = res;
    }
    if (tid >= 512 && tid < 576) {
        int t2 = tid - 512; int s = t2 >> 4, cls = t2 & 15;
        out[49152 + (size_t)b * 4096 + (size_t)cls * 256 + tloc4 + s] = (float)sh->cnt[s * 16 + cls];
    }
}

extern "C" void kernel_launch(void* const* d_in, const int* in_sizes, int n_in,
                              void* d_out, int out_size) {
    const float* x    = (const float*)d_in[0];
    const float* feat = (const float*)d_in[1];
    const float* sdf  = (const float*)d_in[2];
    const float* Wf   = (const float*)d_in[3];
    const float* bf   = (const float*)d_in[4];
    const float* Wsdf = (const float*)d_in[5];
    const float* bsdf = (const float*)d_in[6];
    const int*   gt   = (const int*)d_in[7];
    float* out = (float*)d_out;

    size_t smem = sizeof(SmemLayout);
    cudaFuncSetAttribute(cluster_kernel, cudaFuncAttributeMaxDynamicSharedMemorySize, (int)smem);
    cluster_kernel<<<128, 1024, smem>>>(x, feat, sdf, Wf, bf, Wsdf, bsdf, gt, out);
}

// round 13
// speedup vs baseline: 1.5342x; 1.1416x over previous
#include <cuda_runtime.h>
#include <math.h>

// B=2, DIM=32, H=W=512, FOLD=8, P=2, HDIM=96, NCLS=16, CV=96
// S=4, tile 64x64, N=4096 px/tile, 128 tiles.
// out: center_feat [2,256,96]=49152 | labels [2,16,256]=8192 | spix_map [2,512,512]=524288

struct SmemLayout {
    float4 scst[4096];    // per-pixel static (x+sdf) scores
    float4 a4[2][1024];   // double-buffered per-chunk weights
    float4 cen4[160];     // pooled quadrant means: x[0..31], sdf[32..62], feat[63..158]
    float4 cdf4[96];
    float4 csf4[96];
    float4 g4[32];
    float4 q4[32];
    float4 cpf1[96];
    float4 num4[96];
    float4 onum4[96];
    float Cs[4], n0[4], n1[4], den[4], wden[4];
    int   cnt[4][16];
};

__device__ __forceinline__ float wredsum(float v) {
#pragma unroll
    for (int o = 16; o; o >>= 1) v += __shfl_xor_sync(0xffffffffu, v, o);
    return v;
}

__global__ void __launch_bounds__(1024, 1)
cluster_kernel(const float* __restrict__ x, const float* __restrict__ feat,
               const float* __restrict__ sdf, const float* __restrict__ Wf,
               const float* __restrict__ bf, const float* __restrict__ Wsdf,
               const float* __restrict__ bsdf, const int* __restrict__ gt,
               float* __restrict__ out)
{
    extern __shared__ char smem_raw[];
    SmemLayout* sh = reinterpret_cast<SmemLayout*>(smem_raw);

    const int tile = blockIdx.x;
    const int b    = tile >> 6;
    const int f1   = (tile >> 3) & 7;
    const int f2   = tile & 7;
    const int tid  = threadIdx.x;
    const int wid  = tid >> 5;
    const int lane = tid & 31;
    const int base = f1 * 64 * 512 + f2 * 64;

    if (tid < 4) { sh->den[tid] = 0.f; sh->wden[tid] = 0.f; }
    if (tid < 64) sh->cnt[tid >> 4][tid & 15] = 0;

    // ---------------- Phase 1: quadrant pooling (float4) ----------------
    for (int ch = wid; ch < 159; ch += 32) {
        const float* src;
        if (ch < 32)      src = x    + (((size_t)(b * 32 + ch)) << 18);
        else if (ch < 63) src = sdf  + (((size_t)(b * 31 + (ch - 32))) << 18);
        else              src = feat + (((size_t)(b * 96 + (ch - 63))) << 18);
        src += base;
        float acc[4];
#pragma unroll
        for (int q = 0; q < 4; q++) {
            const float* p2 = src + (q >> 1) * 32 * 512 + (q & 1) * 32
                                  + (lane >> 3) * 512 + (lane & 7) * 4;
            float a = 0.f;
#pragma unroll
            for (int i = 0; i < 8; i++) {
                float4 v = *(const float4*)(p2 + i * 4 * 512);
                a += (v.x + v.y) + (v.z + v.w);
            }
            acc[q] = a;
        }
#pragma unroll
        for (int q = 0; q < 4; q++) acc[q] = wredsum(acc[q]);
        if (lane == 0)
            sh->cen4[ch] = make_float4(acc[0] * (1.f / 1024.f), acc[1] * (1.f / 1024.f),
                                       acc[2] * (1.f / 1024.f), acc[3] * (1.f / 1024.f));
    }
    __syncthreads();

    // ---------------- Phase 2: per-tile derived quantities ----------------
    if (tid < 384) {
        int j = tid >> 2, s = tid & 3;
        const float* wr = Wf + j * 32;
        float a = bf[j];
#pragma unroll 8
        for (int c = 0; c < 32; c++) a = fmaf(wr[c], ((const float*)&sh->cen4[c])[s], a);
        ((float*)&sh->cdf4[j])[s] = a;
        const float* wr2 = Wsdf + j * 31;
        float a2 = bsdf[j];
#pragma unroll 8
        for (int c = 0; c < 31; c++) a2 = fmaf(wr2[c], ((const float*)&sh->cen4[32 + c])[s], a2);
        ((float*)&sh->csf4[j])[s] = a2;
    }
    __syncthreads();
    if (tid < 128) {
        int c = tid >> 2, s = tid & 3;
        float a = 0.f;
        for (int j = 0; j < 96; j++) a = fmaf(Wf[j * 32 + c], ((const float*)&sh->cdf4[j])[s], a);
        ((float*)&sh->g4[c])[s] = a;
    } else if (tid < 252) {
        int t2 = tid - 128; int c = t2 >> 2, s = t2 & 3;
        float a = 0.f;
        for (int j = 0; j < 96; j++) a = fmaf(Wsdf[j * 31 + c], ((const float*)&sh->csf4[j])[s], a);
        ((float*)&sh->q4[c])[s] = a;
    } else if (tid >= 256 && tid < 260) {
        int s = tid - 256;
        float kf = 0.f, ks = 0.f, nd = 0.f, ns = 0.f;
        for (int j = 0; j < 96; j++) {
            float d = ((const float*)&sh->cdf4[j])[s];
            float e = ((const float*)&sh->csf4[j])[s];
            kf = fmaf(bf[j], d, kf); ks = fmaf(bsdf[j], e, ks);
            nd = fmaf(d, d, nd);     ns = fmaf(e, e, ns);
        }
        sh->Cs[s] = 2.f * kf + 2.f * ks - nd - ns;
    } else if (tid >= 260 && tid < 264) {
        int s = tid - 260;
        float a = 0.f;
        for (int c = 0; c < 96; c++) { float v = ((const float*)&sh->cen4[63 + c])[s]; a = fmaf(v, v, a); }
        sh->n0[s] = a;
    }
    __syncthreads();

    const float C0 = sh->Cs[0], C1 = sh->Cs[1], C2 = sh->Cs[2], C3 = sh->Cs[3];
    const float m0 = sh->n0[0], m1 = sh->n0[1], m2 = sh->n0[2], m3 = sh->n0[3];

    const float* xb = x    + (((size_t)(b * 32)) << 18) + base;
    const float* sb = sdf  + (((size_t)(b * 31)) << 18) + base;
    const float* fb = feat + (((size_t)(b * 96)) << 18) + base;

    // per-warp accumulation channel base pointers (channels wid, wid+32, wid+64)
    const float* fc0 = fb + (((size_t)(wid))      << 18);
    const float* fc1 = fb + (((size_t)(wid + 32)) << 18);
    const float* fc2 = fb + (((size_t)(wid + 64)) << 18);

    // ---------------- Phase 3: iter-0 scores + softmax + centroid update ----------------
    float pd0 = 0.f, pd1 = 0.f, pd2 = 0.f, pd3 = 0.f;
    float an[12];
#pragma unroll
    for (int k = 0; k < 12; k++) an[k] = 0.f;

    for (int ck = 0; ck < 4; ck++) {
        const int bb  = ck & 1;
        const int p   = ck * 1024 + tid;
        const int pix = (p >> 6) * 512 + (p & 63);
        float r0 = 0.f, r1 = 0.f, r2 = 0.f, r3 = 0.f;
        {
            const float* xp = xb + pix;
#pragma unroll 8
            for (int c = 0; c < 32; c++) {
                float v = xp[((size_t)c) << 18];
                float4 g = sh->g4[c];
                r0 = fmaf(v, g.x, r0); r1 = fmaf(v, g.y, r1);
                r2 = fmaf(v, g.z, r2); r3 = fmaf(v, g.w, r3);
            }
            const float* sp = sb + pix;
#pragma unroll 8
            for (int c = 0; c < 31; c++) {
                float v = sp[((size_t)c) << 18];
                float4 g = sh->q4[c];
                r0 = fmaf(v, g.x, r0); r1 = fmaf(v, g.y, r1);
                r2 = fmaf(v, g.z, r2); r3 = fmaf(v, g.w, r3);
            }
        }
        float st0 = 2.f * r0 + C0, st1 = 2.f * r1 + C1;
        float st2 = 2.f * r2 + C2, st3 = 2.f * r3 + C3;
        sh->scst[p] = make_float4(st0, st1, st2, st3);

        float f0 = 0.f, f1_ = 0.f, f2_ = 0.f, f3 = 0.f;
        {
            const float* fp = fb + pix;
#pragma unroll 8
            for (int c = 0; c < 96; c++) {
                float v = fp[((size_t)c) << 18];
                float4 g = sh->cen4[63 + c];
                f0 = fmaf(v, g.x, f0); f1_ = fmaf(v, g.y, f1_);
                f2_ = fmaf(v, g.z, f2_); f3 = fmaf(v, g.w, f3);
            }
        }
        float q0 = st0 + 2.f * f0 - m0;
        float q1 = st1 + 2.f * f1_ - m1;
        float q2 = st2 + 2.f * f2_ - m2;
        float q3 = st3 + 2.f * f3 - m3;
        float mx = fmaxf(fmaxf(q0, q1), fmaxf(q2, q3));
        float e0 = __expf(q0 - mx), e1 = __expf(q1 - mx);
        float e2 = __expf(q2 - mx), e3 = __expf(q3 - mx);
        float inv = 1.f / (e0 + e1 + e2 + e3);
        float a0 = e0 * inv, a1 = e1 * inv, a2 = e2 * inv, a3 = e3 * inv;
        sh->a4[bb][tid] = make_float4(a0, a1, a2, a3);
        pd0 += a0; pd1 += a1; pd2 += a2; pd3 += a3;
        __syncthreads();
        // accumulation: one a4 read shared across the warp's 3 owned channels
        {
            const int coff = ck * 16 * 512 + lane;
#pragma unroll 4
            for (int seg = 0; seg < 32; seg++) {
                const int off = coff + (seg >> 1) * 512 + (seg & 1) * 32;
                float4 a = sh->a4[bb][seg * 32 + lane];
                float v0 = fc0[off], v1 = fc1[off], v2 = fc2[off];
                an[0]  = fmaf(v0, a.x, an[0]);  an[1]  = fmaf(v0, a.y, an[1]);
                an[2]  = fmaf(v0, a.z, an[2]);  an[3]  = fmaf(v0, a.w, an[3]);
                an[4]  = fmaf(v1, a.x, an[4]);  an[5]  = fmaf(v1, a.y, an[5]);
                an[6]  = fmaf(v1, a.z, an[6]);  an[7]  = fmaf(v1, a.w, an[7]);
                an[8]  = fmaf(v2, a.x, an[8]);  an[9]  = fmaf(v2, a.y, an[9]);
                an[10] = fmaf(v2, a.z, an[10]); an[11] = fmaf(v2, a.w, an[11]);
            }
        }
        // no trailing barrier: next chunk uses the other a4 buffer
    }
    pd0 = wredsum(pd0); pd1 = wredsum(pd1); pd2 = wredsum(pd2); pd3 = wredsum(pd3);
    if (lane == 0) {
        atomicAdd(&sh->den[0], pd0); atomicAdd(&sh->den[1], pd1);
        atomicAdd(&sh->den[2], pd2); atomicAdd(&sh->den[3], pd3);
    }
#pragma unroll
    for (int k = 0; k < 12; k++) an[k] = wredsum(an[k]);
    if (lane == 0) {
#pragma unroll
        for (int k = 0; k < 3; k++)
            sh->num4[wid + k * 32] = make_float4(an[k * 4 + 0], an[k * 4 + 1],
                                                 an[k * 4 + 2], an[k * 4 + 3]);
    }
    __syncthreads();
    if (tid < 96) {
        float4 nv = sh->num4[tid];
        float4 o;
        o.x = nv.x / (sh->den[0] + 1e-16f);
        o.y = nv.y / (sh->den[1] + 1e-16f);
        o.z = nv.z / (sh->den[2] + 1e-16f);
        o.w = nv.w / (sh->den[3] + 1e-16f);
        sh->cpf1[tid] = o;
    }
    __syncthreads();
    if (tid < 4) {
        float a = 0.f;
        for (int c = 0; c < 96; c++) { float v = ((const float*)&sh->cpf1[c])[tid]; a = fmaf(v, v, a); }
        sh->n1[tid] = a;
    }
    __syncthreads();

    const float u0 = sh->n1[0], u1 = sh->n1[1], u2 = sh->n1[2], u3 = sh->n1[3];
    const int tloc4 = (f1 * 8 + f2) * 4;
    const int* gtb = gt + (size_t)b * 262144 + base;
    float* spix = out + 57344 + (size_t)b * 262144 + base;

    // ---------------- Phase 4: iter-1, argmax, masked accumulation ----------------
    float pw0 = 0.f, pw1 = 0.f, pw2 = 0.f, pw3 = 0.f;
    float ao[12];
#pragma unroll
    for (int k = 0; k < 12; k++) ao[k] = 0.f;

    for (int ck = 0; ck < 4; ck++) {
        const int bb  = ck & 1;
        const int p   = ck * 1024 + tid;
        const int pix = (p >> 6) * 512 + (p & 63);
        float4 st = sh->scst[p];
        float f0 = 0.f, f1_ = 0.f, f2_ = 0.f, f3 = 0.f;
        const float* fp = fb + pix;
#pragma unroll 8
        for (int c = 0; c < 96; c++) {
            float v = fp[((size_t)c) << 18];
            float4 g = sh->cpf1[c];
            f0 = fmaf(v, g.x, f0); f1_ = fmaf(v, g.y, f1_);
            f2_ = fmaf(v, g.z, f2_); f3 = fmaf(v, g.w, f3);
        }
        float q0 = st.x + 2.f * f0 - u0;
        float q1 = st.y + 2.f * f1_ - u1;
        float q2 = st.z + 2.f * f2_ - u2;
        float q3 = st.w + 2.f * f3 - u3;
        int ss = 0; float best = q0;                 // first-max tie rule (matches jnp.argmax)
        if (q1 > best) { best = q1; ss = 1; }
        if (q2 > best) { best = q2; ss = 2; }
        if (q3 > best) { best = q3; ss = 3; }
        float w = 1.f / (__expf(q0 - best) + __expf(q1 - best)
                       + __expf(q2 - best) + __expf(q3 - best));
        float4 mm;
        mm.x = (ss == 0) ? w : 0.f; mm.y = (ss == 1) ? w : 0.f;
        mm.z = (ss == 2) ? w : 0.f; mm.w = (ss == 3) ? w : 0.f;
        sh->a4[bb][tid] = mm;
        pw0 += mm.x; pw1 += mm.y; pw2 += mm.z; pw3 += mm.w;
        int gv = __ldcs(gtb + pix);
        atomicAdd(&sh->cnt[ss][gv], 1);
        __stcs(spix + pix, (float)(tloc4 + ss));
        __syncthreads();
        {
            const int coff = ck * 16 * 512 + lane;
#pragma unroll 4
            for (int seg = 0; seg < 32; seg++) {
                const int off = coff + (seg >> 1) * 512 + (seg & 1) * 32;
                float4 a = sh->a4[bb][seg * 32 + lane];
                float v0 = fc0[off], v1 = fc1[off], v2 = fc2[off];
                ao[0]  = fmaf(v0, a.x, ao[0]);  ao[1]  = fmaf(v0, a.y, ao[1]);
                ao[2]  = fmaf(v0, a.z, ao[2]);  ao[3]  = fmaf(v0, a.w, ao[3]);
                ao[4]  = fmaf(v1, a.x, ao[4]);  ao[5]  = fmaf(v1, a.y, ao[5]);
                ao[6]  = fmaf(v1, a.z, ao[6]);  ao[7]  = fmaf(v1, a.w, ao[7]);
                ao[8]  = fmaf(v2, a.x, ao[8]);  ao[9]  = fmaf(v2, a.y, ao[9]);
                ao[10] = fmaf(v2, a.z, ao[10]); ao[11] = fmaf(v2, a.w, ao[11]);
            }
        }
    }
    pw0 = wredsum(pw0); pw1 = wredsum(pw1); pw2 = wredsum(pw2); pw3 = wredsum(pw3);
    if (lane == 0) {
        atomicAdd(&sh->wden[0], pw0); atomicAdd(&sh->wden[1], pw1);
        atomicAdd(&sh->wden[2], pw2); atomicAdd(&sh->wden[3], pw3);
    }
#pragma unroll
    for (int k = 0; k < 12; k++) ao[k] = wredsum(ao[k]);
    if (lane == 0) {
#pragma unroll
        for (int k = 0; k < 3; k++)
            sh->onum4[wid + k * 32] = make_float4(ao[k * 4 + 0], ao[k * 4 + 1],
                                                  ao[k * 4 + 2], ao[k * 4 + 3]);
    }
    __syncthreads();

    // ---------------- Phase 5: final writes ----------------
    if (tid < 384) {
        int c = tid >> 2, s = tid & 3;
        float ov = ((const float*)&sh->onum4[c])[s];
        float vc = ((const float*)&sh->cen4[63 + c])[s];
        float res = (ov + vc) / (sh->wden[s] + 1.f);
        out[(size_t)b * 24576 + (size_t)(tloc4 + s) * 96 + c] = res;
    }
    if (tid >= 512 && tid < 576) {
        int t2 = tid - 512; int s = t2 >> 4, cls = t2 & 15;
        out[49152 + (size_t)b * 4096 + (size_t)cls * 256 + tloc4 + s] = (float)sh->cnt[s][cls];
    }
}

extern "C" void kernel_launch(void* const* d_in, const int* in_sizes, int n_in,
                              void* d_out, int out_size) {
    const float* x    = (const float*)d_in[0];
    const float* feat = (const float*)d_in[1];
    const float* sdf  = (const float*)d_in[2];
    const float* Wf   = (const float*)d_in[3];
    const float* bf   = (const float*)d_in[4];
    const float* Wsdf = (const float*)d_in[5];
    const float* bsdf = (const float*)d_in[6];
    const int*   gt   = (const int*)d_in[7];
    float* out = (float*)d_out;

    size_t smem = sizeof(SmemLayout);
    cudaFuncSetAttribute(cluster_kernel, cudaFuncAttributeMaxDynamicSharedMemorySize, (int)smem);
    cluster_kernel<<<128, 1024, smem>>>(x, feat, sdf, Wf, bf, Wsdf, bsdf, gt, out);
}